// round 8
// baseline (speedup 1.0000x reference)
#include <cuda_runtime.h>
#include <math.h>

#define TT 512
#define BB 128
#define DD 128
#define HH 256
#define CC 10
#define G4 1024
#define MROWS (TT*BB)
#define NCTA 128

// ---------------- static device scratch (no runtime allocation) ----------------
__device__ float g_e  [(size_t)MROWS * DD];        //  32 MB embedded inputs [t*B+b, D]
__device__ float g_XwF[(size_t)MROWS * G4];        // 256 MB x@W fwd (reused layer 2)
__device__ float g_XwB[(size_t)MROWS * G4];        // 256 MB x@W bwd (reused layer 2)
__device__ float g_seq[(size_t)MROWS * 2 * HH];    // 128 MB layer-1 output sequence
__device__ float g_state[4 * BB * HH];             // per dir: h parity buf0, buf1
__device__ unsigned g_flags[NCTA * 32];            // per-CTA publication epoch, 128B lines

// packed dual-fp32 FMA (recurrence inner loop)
__device__ __forceinline__ void ffma2(float2 &d, float2 a, float2 b) {
    asm("fma.rn.f32x2 %0, %1, %2, %0;"
        : "+l"(*reinterpret_cast<unsigned long long*>(&d))
        : "l"(*reinterpret_cast<unsigned long long*>(&a)),
          "l"(*reinterpret_cast<unsigned long long*>(&b)));
}

__device__ __forceinline__ float sigf(float x) {
    return __fdividef(1.0f, 1.0f + __expf(-x));
}
__device__ __forceinline__ float tanhfast(float x) {
    return __fdividef(2.0f, 1.0f + __expf(-2.0f * x)) - 1.0f;
}

__device__ __forceinline__ unsigned ld_acq(const unsigned* p) {
    unsigned v;
    asm volatile("ld.acquire.gpu.global.u32 %0, [%1];" : "=r"(v) : "l"(p));
    return v;
}
__device__ __forceinline__ void st_rel(unsigned* p, unsigned v) {
    asm volatile("st.release.gpu.global.u32 [%0], %1;" :: "l"(p), "r"(v) : "memory");
}

// cp.async 16B: GMEM -> SMEM without register staging (GEMM path)
__device__ __forceinline__ void cpa16(unsigned dst, const void* src) {
    asm volatile("cp.async.cg.shared.global [%0], [%1], 16;" :: "r"(dst), "l"(src));
}
#define CPA_COMMIT() asm volatile("cp.async.commit_group;")
#define CPA_WAIT0()  asm volatile("cp.async.wait_group 0;")

// fp32 -> tf32
__device__ __forceinline__ unsigned f2tf32(float x) {
    unsigned r; asm("cvt.rna.tf32.f32 %0, %1;" : "=r"(r) : "f"(x)); return r;
}

// m16n8k8 tf32 MMA, fp32 accumulate
__device__ __forceinline__ void mma_tf32(float* c, const unsigned* a, const unsigned* b) {
    asm("mma.sync.aligned.m16n8k8.row.col.f32.tf32.tf32.f32 "
        "{%0,%1,%2,%3}, {%4,%5,%6,%7}, {%8,%9}, {%0,%1,%2,%3};"
        : "+f"(c[0]), "+f"(c[1]), "+f"(c[2]), "+f"(c[3])
        : "r"(a[0]), "r"(a[1]), "r"(a[2]), "r"(a[3]), "r"(b[0]), "r"(b[1]));
}

// ---------------- embedding gather ----------------
__global__ void embed_k(const int* __restrict__ x, const float* __restrict__ emb) {
    int gid = blockIdx.x * blockDim.x + threadIdx.x;
    int r  = gid >> 5;
    int c4 = gid & 31;
    int t  = r >> 7;
    int b  = r & 127;
    int tok = x[b * TT + t];
    reinterpret_cast<float4*>(g_e)[(size_t)r * 32 + c4] =
        reinterpret_cast<const float4*>(emb)[(size_t)tok * 32 + c4];
}

// ---------------- 3xTF32 tensor-core GEMM + bias (unchanged from R7) ----------------
#define AS_LD 20
#define BS_LD 136
__global__ __launch_bounds__(256) void gemm_k(int a_sel, int c_sel,
        const float* __restrict__ W, const float* __restrict__ bias, int K)
{
    const float* A = a_sel ? g_seq : g_e;
    float*       C = c_sel ? g_XwB : g_XwF;

    __shared__ __align__(16) float As[2][128][AS_LD];
    __shared__ __align__(16) float Bs[2][16][BS_LD];

    const int m0   = blockIdx.x * 128;
    const int n0   = blockIdx.y * 128;
    const int tid  = threadIdx.x;
    const int lane = tid & 31;
    const int warp = tid >> 5;
    const int gid  = lane >> 2;
    const int tig  = lane & 3;
    const int wm   = warp & 3;
    const int wn   = warp >> 2;

    const unsigned sA = (unsigned)__cvta_generic_to_shared(&As[0][0][0]);
    const unsigned sB = (unsigned)__cvta_generic_to_shared(&Bs[0][0][0]);
    const unsigned bufA = 128 * AS_LD * 4;
    const unsigned bufB = 16 * BS_LD * 4;

    float acc[2][8][4];
#pragma unroll
    for (int mb = 0; mb < 2; ++mb)
#pragma unroll
        for (int nb = 0; nb < 8; ++nb)
#pragma unroll
            for (int r = 0; r < 4; ++r) acc[mb][nb][r] = 0.f;

    const int nk = K >> 4;

    auto load_tile = [&](int buf, int kt) {
#pragma unroll
        for (int i = 0; i < 2; ++i) {
            int id = tid + i * 256;
            int r = id >> 2, kq = id & 3;
            cpa16(sA + buf * bufA + (unsigned)((r * AS_LD + kq * 4) * 4),
                  A + (size_t)(m0 + r) * K + kt + kq * 4);
        }
#pragma unroll
        for (int i = 0; i < 2; ++i) {
            int id = tid + i * 256;
            int r = id >> 5, c4 = (id & 31) * 4;
            cpa16(sB + buf * bufB + (unsigned)((r * BS_LD + c4) * 4),
                  W + (size_t)(kt + r) * G4 + n0 + c4);
        }
        CPA_COMMIT();
    };

    load_tile(0, 0);
    CPA_WAIT0();
    __syncthreads();

    for (int kt = 0; kt < nk; ++kt) {
        const int cur = kt & 1;
        const bool more = (kt + 1) < nk;
        if (more) load_tile(cur ^ 1, (kt + 1) << 4);

#pragma unroll
        for (int kh = 0; kh < 2; ++kh) {
            const int k0 = kh * 8;
            unsigned ahi[2][4], alo[2][4];
#pragma unroll
            for (int mb = 0; mb < 2; ++mb) {
                const int rbase = wm * 32 + mb * 16 + gid;
#pragma unroll
                for (int r = 0; r < 4; ++r) {
                    float v = As[cur][rbase + (r & 1) * 8][k0 + tig + (r >> 1) * 4];
                    unsigned h = f2tf32(v);
                    ahi[mb][r] = h;
                    alo[mb][r] = f2tf32(v - __uint_as_float(h));
                }
            }
#pragma unroll
            for (int nb = 0; nb < 8; ++nb) {
                const int nc = wn * 64 + nb * 8 + gid;
                float b0 = Bs[cur][k0 + tig][nc];
                float b1 = Bs[cur][k0 + tig + 4][nc];
                unsigned bh[2], bl[2];
                bh[0] = f2tf32(b0); bl[0] = f2tf32(b0 - __uint_as_float(bh[0]));
                bh[1] = f2tf32(b1); bl[1] = f2tf32(b1 - __uint_as_float(bh[1]));
#pragma unroll
                for (int mb = 0; mb < 2; ++mb) mma_tf32(acc[mb][nb], ahi[mb], bh);
#pragma unroll
                for (int mb = 0; mb < 2; ++mb) mma_tf32(acc[mb][nb], ahi[mb], bl);
#pragma unroll
                for (int mb = 0; mb < 2; ++mb) mma_tf32(acc[mb][nb], alo[mb], bh);
            }
        }
        if (more) {
            CPA_WAIT0();
            __syncthreads();
        }
    }

#pragma unroll
    for (int mb = 0; mb < 2; ++mb) {
        const int row0 = m0 + wm * 32 + mb * 16 + gid;
#pragma unroll
        for (int nb = 0; nb < 8; ++nb) {
            const int col = n0 + wn * 64 + nb * 8 + tig * 2;
            float2 bv = *reinterpret_cast<const float2*>(bias + col);
            float2 v0 = make_float2(acc[mb][nb][0] + bv.x, acc[mb][nb][1] + bv.y);
            float2 v1 = make_float2(acc[mb][nb][2] + bv.x, acc[mb][nb][3] + bv.y);
            *reinterpret_cast<float2*>(C + (size_t)row0 * G4 + col)       = v0;
            *reinterpret_cast<float2*>(C + (size_t)(row0 + 8) * G4 + col) = v1;
        }
    }
}

// ---------------- persistent bidirectional LSTM: flag-pipelined dataflow ----------------
// bid = dir*64 + bt*8 + nt. CTA (dir,bt,nt) computes cols [nt*32,+32) x 4 gates for
// batch rows [bt*16,+16). Per step, instead of a group barrier:
//  - producer: stcg h-slice -> hbuf(par^1), threadfence, syncthreads, tid0 release-
//    stores its epoch flag (pub s+2 = "h(s) readable").
//  - consumer: 256-k reduction in 8 chunks of 32; chunk nt (own h) from smem selfb
//    (no wait); remote chunk c gated on producer c's flag >= base+s+1, flag value
//    prefetched one chunk earlier so the check is hidden; chunk data LDG->STS
//    double-buffered under compute.
// Safety: a CTA writes h(s) only after consuming all 8 flags >= base+s+1, i.e. all
// step-(s-1) readers of the target parity buffer are done. Flags are monotone and
// persist across replays (base re-read each launch).
__global__ __launch_bounds__(128) void lstm_persist_k(
        const float* __restrict__ Uf, const float* __restrict__ Ub, int write_seq)
{
    extern __shared__ float Us[];                     // [256][128] U slice
    __shared__ __align__(16) float selfb[16][36];     // own h chunk
    __shared__ __align__(16) float stage[2][16][36];  // remote chunk stages

    const int bid = blockIdx.x;
    const int dir = bid >> 6;
    const int bt  = (bid >> 3) & 7;
    const int nt  = bid & 7;
    const int tid = threadIdx.x;

    const float* U  = dir ? Ub : Uf;
    const float* Xw = dir ? g_XwB : g_XwF;
    float* hbuf = g_state + (size_t)dir * 2 * BB * HH;
    unsigned* gflags = g_flags + (size_t)(dir * 64 + bt * 8) * 32;  // producer c -> +c*32
    unsigned* myflag = gflags + nt * 32;

    const unsigned base = *(volatile unsigned*)myflag;

    // load U slice: Us[k*128 + g*32 + ln] = U[k*G4 + g*HH + nt*32 + ln]
    for (int i = tid; i < 256 * 32; i += 128) {
        int k = i >> 5;
        int col = (i & 31) * 4;
        int g = col >> 5, ln = col & 31;
        *reinterpret_cast<float4*>(&Us[k * 128 + col]) =
            *reinterpret_cast<const float4*>(U + (size_t)k * G4 + g * HH + nt * 32 + ln);
    }

    // publication 1: zeros (h(-1)) into parity buf0 patch + local selfb
    for (int i = tid; i < 16 * 32; i += 128) {
        int r = i >> 5, cc = i & 31;
        __stcg(hbuf + (size_t)(bt * 16 + r) * HH + nt * 32 + cc, 0.f);
        selfb[r][cc] = 0.f;
    }
    __threadfence();
    __syncthreads();
    if (tid == 0) st_rel(myflag, base + 1);

    const int b_half = tid >> 4;
    const int n_grp  = tid & 15;
    const int nloc   = n_grp * 2;
    const int ngl    = nt * 32 + nloc;
    const int r0     = bt * 16 + b_half * 2;
    const int rowj   = tid >> 3;      // chunk LDG/STS row 0..15
    const int segj   = tid & 7;       // 16B segment 0..7

    float2 cst[2] = {make_float2(0.f, 0.f), make_float2(0.f, 0.f)};

    for (int s = 0; s < TT; ++s) {
        const int t   = dir ? (TT - 1 - s) : s;
        const int par = s & 1;
        const float* hRead  = hbuf + (size_t)par * BB * HH;
        float*       hWrite = hbuf + (size_t)(par ^ 1) * BB * HH;
        const unsigned tgt = base + (unsigned)s + 1;

        // xW for my 2 rows x 2 cols x 4 gates (DRAM; consumed after the k-loop)
        const float* xw0 = Xw + ((size_t)t * BB + r0) * G4 + ngl;
        const float* xw1 = xw0 + G4;
        float2 x0[4], x1[4];
#pragma unroll
        for (int g = 0; g < 4; ++g) {
            x0[g] = *reinterpret_cast<const float2*>(xw0 + g * HH);
            x1[g] = *reinterpret_cast<const float2*>(xw1 + g * HH);
        }

        float2 acc[4][2];
#pragma unroll
        for (int g = 0; g < 4; ++g) {
            acc[g][0] = make_float2(0.f, 0.f);
            acc[g][1] = make_float2(0.f, 0.f);
        }

        // flag value for chunk index 1 (producer (nt+1)&7), checked at iter 0
        unsigned fv = ld_acq(gflags + ((nt + 1) & 7) * 32);

        for (int i = 0; i < 8; ++i) {
            const int ci = (nt + i) & 7;
            float4 ldv;
            if (i < 7) {
                const int cn = (nt + i + 1) & 7;
                if ((int)(fv - tgt) < 0) {               // slow path: producer behind
                    const unsigned* fp = gflags + cn * 32;
                    do { fv = ld_acq(fp); } while ((int)(fv - tgt) < 0);
                }
                ldv = __ldcg(reinterpret_cast<const float4*>(
                    hRead + (size_t)(bt * 16 + rowj) * HH + cn * 32 + segj * 4));
                if (i < 6)                               // prefetch next flag
                    fv = ld_acq(gflags + ((nt + i + 2) & 7) * 32);
            }
            // compute chunk ci (32 k-iters)
            const float (*cb)[36] = (i == 0) ? selfb : stage[i & 1];
            const float* sr0 = cb[b_half * 2];
            const float* sr1 = cb[b_half * 2 + 1];
            const float* Up  = Us + (size_t)(ci * 32) * 128 + nloc;
#pragma unroll 4
            for (int kk = 0; kk < 32; kk += 4) {
                float4 h0v = *reinterpret_cast<const float4*>(sr0 + kk);
                float4 h1v = *reinterpret_cast<const float4*>(sr1 + kk);
                const float h0a[4] = {h0v.x, h0v.y, h0v.z, h0v.w};
                const float h1a[4] = {h1v.x, h1v.y, h1v.z, h1v.w};
#pragma unroll
                for (int j = 0; j < 4; ++j) {
                    const float* row = Up + (size_t)(kk + j) * 128;
                    float2 hh0 = make_float2(h0a[j], h0a[j]);
                    float2 hh1 = make_float2(h1a[j], h1a[j]);
#pragma unroll
                    for (int g = 0; g < 4; ++g) {
                        float2 u2 = *reinterpret_cast<const float2*>(row + g * 32);
                        ffma2(acc[g][0], u2, hh0);
                        ffma2(acc[g][1], u2, hh1);
                    }
                }
            }
            if (i < 7) {
                *reinterpret_cast<float4*>(&stage[(i + 1) & 1][rowj][segj * 4]) = ldv;
                __syncthreads();
            }
        }

        // gates + state update + publish
#pragma unroll
        for (int bb = 0; bb < 2; ++bb) {
            const float2* xg = bb ? x1 : x0;
            float zi0 = acc[0][bb].x + xg[0].x, zi1 = acc[0][bb].y + xg[0].y;
            float zf0 = acc[1][bb].x + xg[1].x, zf1 = acc[1][bb].y + xg[1].y;
            float zg0 = acc[2][bb].x + xg[2].x, zg1 = acc[2][bb].y + xg[2].y;
            float zo0 = acc[3][bb].x + xg[3].x, zo1 = acc[3][bb].y + xg[3].y;
            float c0 = sigf(zf0) * cst[bb].x + sigf(zi0) * tanhfast(zg0);
            float c1 = sigf(zf1) * cst[bb].y + sigf(zi1) * tanhfast(zg1);
            cst[bb] = make_float2(c0, c1);
            float h0 = sigf(zo0) * tanhfast(c0);
            float h1 = sigf(zo1) * tanhfast(c1);
            int r = r0 + bb;
            __stcg(reinterpret_cast<float2*>(hWrite + (size_t)r * HH + ngl),
                   make_float2(h0, h1));
            selfb[b_half * 2 + bb][nloc]     = h0;     // own chunk for next step
            selfb[b_half * 2 + bb][nloc + 1] = h1;
            if (write_seq)
                *reinterpret_cast<float2*>(
                    g_seq + ((size_t)t * BB + r) * (2 * HH) + dir * HH + ngl) =
                    make_float2(h0, h1);
        }
        __threadfence();
        __syncthreads();                 // also guards selfb/stage reuse next step
        if (tid == 0) st_rel(myflag, base + (unsigned)s + 2);
    }
}

// ---------------- final dense + softmax ----------------
__global__ void final_k(const float* __restrict__ Wd, const float* __restrict__ bd,
                        float* __restrict__ out)
{
    int b = blockIdx.x, lane = threadIdx.x;
    const float* hf = g_state;                    // dir0 h(511) lands in parity buf0
    const float* hb = g_state + 2 * BB * HH;
    float acc[CC];
#pragma unroll
    for (int c = 0; c < CC; ++c) acc[c] = 0.f;
    for (int k = lane; k < 2 * HH; k += 32) {
        float hv = (k < HH) ? hf[(size_t)b * HH + k] : hb[(size_t)b * HH + k - HH];
        const float* w = Wd + (size_t)k * CC;
#pragma unroll
        for (int c = 0; c < CC; ++c) acc[c] = fmaf(hv, w[c], acc[c]);
    }
#pragma unroll
    for (int c = 0; c < CC; ++c)
#pragma unroll
        for (int o = 16; o; o >>= 1) acc[c] += __shfl_down_sync(0xffffffffu, acc[c], o);
    if (lane == 0) {
        float m = -1e30f;
#pragma unroll
        for (int c = 0; c < CC; ++c) { acc[c] += bd[c]; m = fmaxf(m, acc[c]); }
        float e[CC], s = 0.f;
#pragma unroll
        for (int c = 0; c < CC; ++c) { e[c] = expf(acc[c] - m); s += e[c]; }
        float inv = 1.f / s;
#pragma unroll
        for (int c = 0; c < CC; ++c) out[b * CC + c] = e[c] * inv;
    }
}

extern "C" void kernel_launch(void* const* d_in, const int* in_sizes, int n_in,
                              void* d_out, int out_size)
{
    const int*   x   = (const int*)  d_in[0];
    const float* emb = (const float*)d_in[1];
    const float* W1f = (const float*)d_in[2];
    const float* U1f = (const float*)d_in[3];
    const float* b1f = (const float*)d_in[4];
    const float* W1b = (const float*)d_in[5];
    const float* U1b = (const float*)d_in[6];
    const float* b1b = (const float*)d_in[7];
    const float* W2f = (const float*)d_in[8];
    const float* U2f = (const float*)d_in[9];
    const float* b2f = (const float*)d_in[10];
    const float* W2b = (const float*)d_in[11];
    const float* U2b = (const float*)d_in[12];
    const float* b2b = (const float*)d_in[13];
    const float* Wd  = (const float*)d_in[14];
    const float* bd  = (const float*)d_in[15];
    float* out = (float*)d_out;

    static int smem_set = 0;
    if (!smem_set) {
        cudaFuncSetAttribute(lstm_persist_k,
                             cudaFuncAttributeMaxDynamicSharedMemorySize, 131072);
        smem_set = 1;
    }

    embed_k<<<(MROWS * 32) / 256, 256>>>(x, emb);

    dim3 gg(MROWS / 128, G4 / 128);

    // layer 1
    gemm_k<<<gg, 256>>>(0, 0, W1f, b1f, DD);
    gemm_k<<<gg, 256>>>(0, 1, W1b, b1b, DD);
    lstm_persist_k<<<NCTA, 128, 131072>>>(U1f, U1b, 1);

    // layer 2
    gemm_k<<<gg, 256>>>(1, 0, W2f, b2f, 2 * HH);
    gemm_k<<<gg, 256>>>(1, 1, W2b, b2b, 2 * HH);
    lstm_persist_k<<<NCTA, 128, 131072>>>(U2f, U2b, 0);

    final_k<<<BB, 32>>>(Wd, bd, out);
}